// round 1
// baseline (speedup 1.0000x reference)
#include <cuda_runtime.h>
#include <cuda_bf16.h>

// Problem constants: B=4, H=16, L=8192, D=64
#define BH_   64
#define L_    8192
#define D_    64
#define H_    16
#define S_    32        // positions per subchunk (one 16-lane group scans this serially)
#define NSUB_ 256       // L_ / S_
#define EPS_  1e-6f

// Scratch: per-(bh, subchunk) sums/prefixes of [ sum_k(64) | sum_kv(64) ]
__device__ float g_sums  [BH_ * NSUB_ * 128];
__device__ float g_prefix[BH_ * NSUB_ * 128];

__device__ __forceinline__ float phi(float x) {
    return x > 0.0f ? x + 1.0f : __expf(x);
}

// ---------------------------------------------------------------------------
// Pass 1: per-subchunk sums of masked phi(k) and masked phi(k)*v.
// Grid: 1024 blocks x 256 threads. thread: d4 = t&15 (float4 column),
// subLocal = t>>4 (16 subchunks per block).
// ---------------------------------------------------------------------------
__global__ void __launch_bounds__(256) la_pass1(
    const float* __restrict__ kp, const float* __restrict__ vp,
    const float* __restrict__ mp)
{
    const int t    = threadIdx.x;
    const int d4   = t & 15;
    const int subL = t >> 4;
    const int blk  = blockIdx.x;
    const int bh   = blk >> 4;
    const int sub  = ((blk & 15) << 4) | subL;
    const int b    = bh >> 4;          // bh / H_
    const int l0   = sub * S_;
    const size_t base = ((size_t)bh * L_ + l0) * D_ + d4 * 4;

    float4 sk  = make_float4(0.f, 0.f, 0.f, 0.f);
    float4 skv = make_float4(0.f, 0.f, 0.f, 0.f);

    #pragma unroll 8
    for (int i = 0; i < S_; ++i) {
        const size_t off = base + (size_t)i * D_;
        float4 kk = *(const float4*)(kp + off);
        float4 vv = *(const float4*)(vp + off);
        float  m  = mp[b * L_ + l0 + i];
        float fx = phi(kk.x) * m, fy = phi(kk.y) * m,
              fz = phi(kk.z) * m, fw = phi(kk.w) * m;
        sk.x += fx; sk.y += fy; sk.z += fz; sk.w += fw;
        // reference: k_masked * v_masked  => phi(k)*m * v*m
        skv.x += fx * (vv.x * m); skv.y += fy * (vv.y * m);
        skv.z += fz * (vv.z * m); skv.w += fw * (vv.w * m);
    }

    float* o = g_sums + ((size_t)bh * NSUB_ + sub) * 128;
    *(float4*)(o + d4 * 4)      = sk;
    *(float4*)(o + 64 + d4 * 4) = skv;
}

// ---------------------------------------------------------------------------
// Pass 2: exclusive prefix over the 256 subchunks, per (bh, c) with c in [0,128).
// Grid: 64 blocks x 128 threads. Loads staged in 16-wide tiles to keep MLP high
// despite the serial accumulation.
// ---------------------------------------------------------------------------
__global__ void __launch_bounds__(128) la_pass2()
{
    const int bh = blockIdx.x;
    const int c  = threadIdx.x;
    const size_t base = (size_t)bh * NSUB_ * 128 + c;

    float run = 0.0f;
    for (int tile = 0; tile < NSUB_ / 16; ++tile) {
        float vals[16];
        #pragma unroll
        for (int j = 0; j < 16; ++j)
            vals[j] = g_sums[base + (size_t)(tile * 16 + j) * 128];
        #pragma unroll
        for (int j = 0; j < 16; ++j) {
            g_prefix[base + (size_t)(tile * 16 + j) * 128] = run;
            run += vals[j];
        }
    }
}

// ---------------------------------------------------------------------------
// Pass 3: each 16-lane group scans its 32-position subchunk with the exclusive
// prefix as initial state. z reduced across the 16 lanes via shfl_xor (offsets
// 8,4,2,1 stay within the 16-lane half-warp).
// ---------------------------------------------------------------------------
__global__ void __launch_bounds__(256) la_pass3(
    const float* __restrict__ qp, const float* __restrict__ kp,
    const float* __restrict__ vp, const float* __restrict__ mp,
    float* __restrict__ op)
{
    const int t    = threadIdx.x;
    const int d4   = t & 15;
    const int subL = t >> 4;
    const int blk  = blockIdx.x;
    const int bh   = blk >> 4;
    const int sub  = ((blk & 15) << 4) | subL;
    const int b    = bh >> 4;
    const int l0   = sub * S_;
    const size_t base = ((size_t)bh * L_ + l0) * D_ + d4 * 4;

    const float* pr = g_prefix + ((size_t)bh * NSUB_ + sub) * 128;
    float4 pk  = *(const float4*)(pr + d4 * 4);
    float4 pkv = *(const float4*)(pr + 64 + d4 * 4);

    #pragma unroll 4
    for (int i = 0; i < S_; ++i) {
        const size_t off = base + (size_t)i * D_;
        float4 kk = *(const float4*)(kp + off);
        float4 vv = *(const float4*)(vp + off);
        float4 qq = *(const float4*)(qp + off);
        float  m  = mp[b * L_ + l0 + i];

        float fkx = phi(kk.x) * m, fky = phi(kk.y) * m,
              fkz = phi(kk.z) * m, fkw = phi(kk.w) * m;
        pk.x += fkx; pk.y += fky; pk.z += fkz; pk.w += fkw;
        pkv.x += fkx * (vv.x * m); pkv.y += fky * (vv.y * m);
        pkv.z += fkz * (vv.z * m); pkv.w += fkw * (vv.w * m);

        float fqx = phi(qq.x), fqy = phi(qq.y),
              fqz = phi(qq.z), fqw = phi(qq.w);

        float z = fqx * pk.x + fqy * pk.y + fqz * pk.z + fqw * pk.w;
        z += __shfl_xor_sync(0xffffffffu, z, 8);
        z += __shfl_xor_sync(0xffffffffu, z, 4);
        z += __shfl_xor_sync(0xffffffffu, z, 2);
        z += __shfl_xor_sync(0xffffffffu, z, 1);
        z = (z + EPS_) * m;          // reference: (dot + eps) * mask
        float rz = 1.0f / z;

        float4 o;
        o.x = fqx * pkv.x * rz; o.y = fqy * pkv.y * rz;
        o.z = fqz * pkv.z * rz; o.w = fqw * pkv.w * rz;
        *(float4*)(op + off) = o;
    }
}

// ---------------------------------------------------------------------------
extern "C" void kernel_launch(void* const* d_in, const int* in_sizes, int n_in,
                              void* d_out, int out_size)
{
    const float* q = (const float*)d_in[0];
    const float* k = (const float*)d_in[1];
    const float* v = (const float*)d_in[2];
    const float* m = (const float*)d_in[3];
    float* out = (float*)d_out;

    la_pass1<<<BH_ * (NSUB_ / 16), 256>>>(k, v, m);
    la_pass2<<<BH_, 128>>>();
    la_pass3<<<BH_ * (NSUB_ / 16), 256>>>(q, k, v, m, out);
}